// round 4
// baseline (speedup 1.0000x reference)
#include <cuda_runtime.h>
#include <cuda_bf16.h>
#include <cstdint>

#define N_TOK 8192
#define DIM   2048
#define HID   8192
#define KSEL  4096

// int8 quantization scales
#define XS    24.0f
#define W1S   1024.0f
#define INV1  (1.0f / (24.0f * 1024.0f))
#define HS    20.0f
#define W2S   2048.0f
#define INV2  (1.0f / (20.0f * 2048.0f))

// ---------------- scratch (device globals; no allocation allowed) -----------
__device__ int8_t g_w1q[(size_t)HID * DIM];   // W1^T [HID][DIM] s8 (xW1S)
__device__ int8_t g_w2q[(size_t)DIM * HID];   // W2^T [DIM][HID] s8 (xW2S)
__device__ int8_t g_xn [(size_t)N_TOK * DIM]; // x_norm s8 (xXS)
__device__ int8_t g_h  [(size_t)KSEL * HID];  // gelu(h) s8 (xHS)
__device__ float    g_logits[N_TOK];
__device__ int      g_sel[KSEL];
__device__ unsigned g_thr_key;
__device__ int      g_cnt_greater;
__device__ int      g_c_gt, g_c_tie;

// ---------------- helpers ---------------------------------------------------
__device__ __forceinline__ float gelu_exact(float v) {
    return 0.5f * v * (1.0f + erff(v * 0.70710678118654752f));
}
__device__ __forceinline__ unsigned float_key(float f) {
    unsigned u = __float_as_uint(f);
    return (u & 0x80000000u) ? ~u : (u | 0x80000000u);
}
__device__ __forceinline__ int q8(float v, float s) {
    int i = __float2int_rn(v * s);
    return max(-127, min(127, i));
}
__device__ __forceinline__ uint32_t pack_s8x4(float a, float b, float c, float d, float s) {
    int ia = q8(a, s), ib = q8(b, s), ic = q8(c, s), id = q8(d, s);
    return (uint32_t)(ia & 0xff) | ((uint32_t)(ib & 0xff) << 8) |
           ((uint32_t)(ic & 0xff) << 16) | ((uint32_t)(id & 0xff) << 24);
}

// ---------------- transpose + fp32->s8 (scaled) ------------------------------
// in: [R][C] f32 ; out: [C][R] s8 bytes, value*scale
template<int R, int C>
__global__ __launch_bounds__(256) void transconvq_kernel(
    const float* __restrict__ in, int8_t* __restrict__ outp, float scale)
{
    __shared__ float t[32][33];
    const int n0 = blockIdx.x * 32;
    const int k0 = blockIdx.y * 32;
    const int tx = threadIdx.x & 31;
    const int ty = threadIdx.x >> 5;
    #pragma unroll
    for (int i = 0; i < 4; i++) {
        int k = k0 + ty + 8 * i;
        t[tx][ty + 8 * i] = in[(size_t)k * C + n0 + tx];
    }
    __syncthreads();
    const int r = threadIdx.x >> 3;
    const int q = (threadIdx.x & 7) * 4;
    uint32_t v = pack_s8x4(t[r][q], t[r][q+1], t[r][q+2], t[r][q+3], scale);
    *reinterpret_cast<uint32_t*>(outp + (size_t)(n0 + r) * R + k0 + q) = v;
}

// ---------------- RMSNorm + router logit + x passthrough ---------------------
__device__ __forceinline__ float block_reduce_sum256(float v, float* red) {
    __syncthreads();
    int lane = threadIdx.x & 31, warp = threadIdx.x >> 5;
    #pragma unroll
    for (int o = 16; o > 0; o >>= 1) v += __shfl_xor_sync(0xffffffffu, v, o);
    if (lane == 0) red[warp] = v;
    __syncthreads();
    if (threadIdx.x == 0) {
        float s = 0.f;
        #pragma unroll
        for (int i = 0; i < 8; i++) s += red[i];
        red[8] = s;
    }
    __syncthreads();
    return red[8];
}

__global__ __launch_bounds__(256) void rmsnorm_router_kernel(
    const float* __restrict__ x, const float* __restrict__ nw,
    const float* __restrict__ rw, float* __restrict__ out)
{
    __shared__ float red[9];
    int row = blockIdx.x;
    int tid = threadIdx.x;
    const float4* x4 = reinterpret_cast<const float4*>(x + (size_t)row * DIM);
    float4 v0 = x4[tid];
    float4 v1 = x4[tid + 256];
    float ss = v0.x*v0.x + v0.y*v0.y + v0.z*v0.z + v0.w*v0.w +
               v1.x*v1.x + v1.y*v1.y + v1.z*v1.z + v1.w*v1.w;
    float tot = block_reduce_sum256(ss, red);
    float rms = rsqrtf(tot * (1.0f / DIM) + 1e-6f);

    float4* o4 = reinterpret_cast<float4*>(out + (size_t)row * DIM);
    uint32_t* xn4 = reinterpret_cast<uint32_t*>(g_xn + (size_t)row * DIM);
    float logit = 0.f;
    {
        int c = tid * 4;
        float n0 = v0.x * rms * nw[c+0];
        float n1 = v0.y * rms * nw[c+1];
        float n2 = v0.z * rms * nw[c+2];
        float n3 = v0.w * rms * nw[c+3];
        logit += n0*rw[c+0] + n1*rw[c+1] + n2*rw[c+2] + n3*rw[c+3];
        xn4[tid] = pack_s8x4(n0, n1, n2, n3, XS);
        o4[tid] = v0;
    }
    {
        int c = (tid + 256) * 4;
        float n0 = v1.x * rms * nw[c+0];
        float n1 = v1.y * rms * nw[c+1];
        float n2 = v1.z * rms * nw[c+2];
        float n3 = v1.w * rms * nw[c+3];
        logit += n0*rw[c+0] + n1*rw[c+1] + n2*rw[c+2] + n3*rw[c+3];
        xn4[tid + 256] = pack_s8x4(n0, n1, n2, n3, XS);
        o4[tid + 256] = v1;
    }
    float lt = block_reduce_sum256(logit, red);
    if (tid == 0) g_logits[row] = lt;
}

// ---------------- exact k-th largest via 4-pass radix select -----------------
__global__ __launch_bounds__(1024) void topk_select_kernel() {
    __shared__ unsigned skey[N_TOK];
    __shared__ int hist[256];
    __shared__ int s_krem, s_bin, s_cnt;
    int tid = threadIdx.x;
    const int NT = 1024;
    for (int i = tid; i < N_TOK; i += NT) skey[i] = float_key(g_logits[i]);
    if (tid == 0) s_krem = KSEL;
    __syncthreads();

    unsigned prefix = 0, mask = 0;
    for (int shift = 24; shift >= 0; shift -= 8) {
        if (tid < 256) hist[tid] = 0;
        __syncthreads();
        for (int i = tid; i < N_TOK; i += NT) {
            unsigned u = skey[i];
            if ((u & mask) == prefix) atomicAdd(&hist[(u >> shift) & 255], 1);
        }
        __syncthreads();
        if (tid == 0) {
            int krem = s_krem, cum = 0, b = 0;
            for (int j = 255; j >= 0; --j) {
                if (cum + hist[j] >= krem) { b = j; break; }
                cum += hist[j];
            }
            s_krem = krem - cum;
            s_bin = b;
        }
        __syncthreads();
        prefix |= ((unsigned)s_bin) << shift;
        mask   |= 0xFFu << shift;
        __syncthreads();
    }
    if (tid == 0) s_cnt = 0;
    __syncthreads();
    int c = 0;
    for (int i = tid; i < N_TOK; i += NT) if (skey[i] > prefix) c++;
    atomicAdd(&s_cnt, c);
    __syncthreads();
    if (tid == 0) {
        g_thr_key = prefix;
        g_cnt_greater = s_cnt;
        g_c_gt = 0; g_c_tie = 0;
    }
}

__global__ void compact_kernel() {
    int i = blockIdx.x * blockDim.x + threadIdx.x;
    if (i >= N_TOK) return;
    unsigned u = float_key(g_logits[i]);
    unsigned thr = g_thr_key;
    if (u > thr) {
        int p = atomicAdd(&g_c_gt, 1);
        g_sel[p] = i;
    } else if (u == thr) {
        int t = atomicAdd(&g_c_tie, 1);
        int need = KSEL - g_cnt_greater;
        if (t < need) g_sel[g_cnt_greater + t] = i;
    }
}

// ====================== INT8 mma.sync GEMM ===================================
// Tile 128(M) x 128(N) x 64(K bytes), 8 warps (4Mx2N), 4-stage cp.async.
#define BM 128
#define BN 128
#define BK 64
#define NSTG 4
#define ROWB 80
#define A_STG (BM * ROWB)
#define B_STG (BN * ROWB)
#define GSMEM_BYTES (NSTG * (A_STG + B_STG))   // 81920

__device__ __forceinline__ void cp16(uint32_t s, const void* g) {
    asm volatile("cp.async.cg.shared.global [%0], [%1], 16;" :: "r"(s), "l"(g));
}
__device__ __forceinline__ void ldmx4(uint32_t& r0, uint32_t& r1, uint32_t& r2, uint32_t& r3, uint32_t a) {
    asm volatile("ldmatrix.sync.aligned.m8n8.x4.shared.b16 {%0,%1,%2,%3}, [%4];"
                 : "=r"(r0), "=r"(r1), "=r"(r2), "=r"(r3) : "r"(a));
}
__device__ __forceinline__ void mma_s8(int* c, const uint32_t* a, uint32_t b0, uint32_t b1) {
    asm volatile("mma.sync.aligned.m16n8k32.row.col.s32.s8.s8.s32 "
                 "{%0,%1,%2,%3},{%4,%5,%6,%7},{%8,%9},{%0,%1,%2,%3};"
                 : "+r"(c[0]), "+r"(c[1]), "+r"(c[2]), "+r"(c[3])
                 : "r"(a[0]), "r"(a[1]), "r"(a[2]), "r"(a[3]), "r"(b0), "r"(b1));
}

// EPI==0: A = g_xn gathered by g_sel, B = g_w1q[HID][DIM], out = g_h (gelu, s8)
// EPI==1: A = g_h,                    B = g_w2q[DIM][HID], out = x + gamma*(acc*INV2+b2)
template<int EPI, int Kdim>
__global__ __launch_bounds__(256, 2) void gemm_i8(
    const float* __restrict__ bias, const float* __restrict__ x,
    const float* __restrict__ gamma, float* __restrict__ out)
{
    extern __shared__ char dsm[];
    const uint32_t smA = (uint32_t)__cvta_generic_to_shared(dsm);
    const uint32_t smB = smA + NSTG * A_STG;
    const int tid = threadIdx.x;
    const int lane = tid & 31;
    const int warp = tid >> 5;
    const int bn = blockIdx.x, bm = blockIdx.y;

    const int8_t* Asrc = (EPI == 0) ? g_xn : g_h;
    const int8_t* Bsrc = (EPI == 0) ? g_w1q : g_w2q;

    const int r0 = tid >> 2;
    const int cb = (tid & 3) * 16;
    const int8_t* ap[2]; uint32_t asw[2];
    const int8_t* bp[2]; uint32_t bsw[2];
    #pragma unroll
    for (int j = 0; j < 2; j++) {
        int r = r0 + 64 * j;
        int gm = bm * BM + r;
        long grow = (EPI == 0) ? (long)g_sel[gm] : (long)gm;
        ap[j] = Asrc + (size_t)grow * Kdim + cb;
        asw[j] = smA + r * ROWB + cb;
        bp[j] = Bsrc + (size_t)(bn * BN + r) * Kdim + cb;
        bsw[j] = smB + r * ROWB + cb;
    }

    auto load_stage = [&](int s, int kt) {
        const size_t ko = (size_t)kt * BK;
        const uint32_t ao = s * A_STG, bo = s * B_STG;
        cp16(asw[0] + ao, ap[0] + ko);
        cp16(asw[1] + ao, ap[1] + ko);
        cp16(bsw[0] + bo, bp[0] + ko);
        cp16(bsw[1] + bo, bp[1] + ko);
        asm volatile("cp.async.commit_group;");
    };

    int acc[2][8][4];
    #pragma unroll
    for (int i = 0; i < 2; i++)
        #pragma unroll
        for (int j = 0; j < 8; j++)
            #pragma unroll
            for (int q = 0; q < 4; q++) acc[i][j][q] = 0;

    const int wm = (warp & 3) * 32;
    const int wn = (warp >> 2) * 64;
    const int frow = lane & 15;
    const int fcol = (lane >> 4) * 16;

    const int KT = Kdim / BK;
    load_stage(0, 0);
    load_stage(1, 1);
    load_stage(2, 2);

    for (int kt = 0; kt < KT; ++kt) {
        const int s = kt & (NSTG - 1);
        asm volatile("cp.async.wait_group %0;" :: "n"(NSTG - 2));
        __syncthreads();   // single barrier: data-ready + WAR for next iter's prefetch

        const uint32_t aBase = smA + s * A_STG;
        const uint32_t bBase = smB + s * B_STG;
        #pragma unroll
        for (int ks = 0; ks < 2; ++ks) {
            uint32_t af[2][4];
            #pragma unroll
            for (int mi = 0; mi < 2; ++mi)
                ldmx4(af[mi][0], af[mi][1], af[mi][2], af[mi][3],
                      aBase + (wm + mi * 16 + frow) * ROWB + fcol + ks * 32);
            #pragma unroll
            for (int ni = 0; ni < 4; ++ni) {
                uint32_t b0, b1, b2, b3;
                ldmx4(b0, b1, b2, b3,
                      bBase + (wn + ni * 16 + frow) * ROWB + fcol + ks * 32);
                #pragma unroll
                for (int mi = 0; mi < 2; ++mi) {
                    mma_s8(acc[mi][2 * ni],     af[mi], b0, b2);
                    mma_s8(acc[mi][2 * ni + 1], af[mi], b1, b3);
                }
            }
        }
        if (kt + NSTG - 1 < KT) load_stage((kt + NSTG - 1) & (NSTG - 1), kt + NSTG - 1);
    }

    // ---------------- epilogue ----------------
    const int r  = lane >> 2;
    const int cc = (lane & 3) * 2;
    if (EPI == 0) {
        #pragma unroll
        for (int mi = 0; mi < 2; ++mi) {
            const int gm0 = bm * BM + wm + mi * 16 + r;
            #pragma unroll
            for (int nj = 0; nj < 8; ++nj) {
                const int gn = bn * BN + wn + nj * 8 + cc;
                const float b0 = bias[gn], b1v = bias[gn + 1];
                float v0 = gelu_exact((float)acc[mi][nj][0] * INV1 + b0);
                float v1 = gelu_exact((float)acc[mi][nj][1] * INV1 + b1v);
                float v2 = gelu_exact((float)acc[mi][nj][2] * INV1 + b0);
                float v3 = gelu_exact((float)acc[mi][nj][3] * INV1 + b1v);
                uint16_t p01 = (uint16_t)((q8(v0, HS) & 0xff) | ((q8(v1, HS) & 0xff) << 8));
                uint16_t p23 = (uint16_t)((q8(v2, HS) & 0xff) | ((q8(v3, HS) & 0xff) << 8));
                *reinterpret_cast<uint16_t*>(&g_h[(size_t)gm0 * HID + gn])       = p01;
                *reinterpret_cast<uint16_t*>(&g_h[(size_t)(gm0 + 8) * HID + gn]) = p23;
            }
        }
    } else {
        #pragma unroll
        for (int mi = 0; mi < 2; ++mi) {
            const int m0 = bm * BM + wm + mi * 16 + r;
            const int tok0 = g_sel[m0];
            const int tok1 = g_sel[m0 + 8];
            #pragma unroll
            for (int nj = 0; nj < 8; ++nj) {
                const int gn = bn * BN + wn + nj * 8 + cc;
                const float bb0 = bias[gn], bb1 = bias[gn + 1];
                const float gg0 = gamma[gn], gg1 = gamma[gn + 1];
                const float* xr0 = x + (size_t)tok0 * DIM + gn;
                const float* xr1 = x + (size_t)tok1 * DIM + gn;
                float2 o0, o1;
                o0.x = xr0[0] + gg0 * ((float)acc[mi][nj][0] * INV2 + bb0);
                o0.y = xr0[1] + gg1 * ((float)acc[mi][nj][1] * INV2 + bb1);
                o1.x = xr1[0] + gg0 * ((float)acc[mi][nj][2] * INV2 + bb0);
                o1.y = xr1[1] + gg1 * ((float)acc[mi][nj][3] * INV2 + bb1);
                *reinterpret_cast<float2*>(out + (size_t)tok0 * DIM + gn) = o0;
                *reinterpret_cast<float2*>(out + (size_t)tok1 * DIM + gn) = o1;
            }
        }
    }
}

// ---------------- launch -----------------------------------------------------
extern "C" void kernel_launch(void* const* d_in, const int* in_sizes, int n_in,
                              void* d_out, int out_size) {
    const float* x     = (const float*)d_in[0];
    const float* nw    = (const float*)d_in[1];
    const float* rw    = (const float*)d_in[2];
    const float* w1    = (const float*)d_in[4];
    const float* b1    = (const float*)d_in[5];
    const float* w2    = (const float*)d_in[6];
    const float* b2    = (const float*)d_in[7];
    const float* gamma = (const float*)d_in[8];
    float* out = (float*)d_out;

    cudaFuncSetAttribute(gemm_i8<0, DIM>, cudaFuncAttributeMaxDynamicSharedMemorySize, GSMEM_BYTES);
    cudaFuncSetAttribute(gemm_i8<1, HID>, cudaFuncAttributeMaxDynamicSharedMemorySize, GSMEM_BYTES);

    int8_t* w1q; cudaGetSymbolAddress((void**)&w1q, g_w1q);
    int8_t* w2q; cudaGetSymbolAddress((void**)&w2q, g_w2q);

    // W1 [DIM][HID] f32 -> g_w1q [HID][DIM] s8 * W1S
    transconvq_kernel<DIM, HID><<<dim3(HID / 32, DIM / 32), 256>>>(w1, w1q, W1S);
    // W2 [HID][DIM] f32 -> g_w2q [DIM][HID] s8 * W2S
    transconvq_kernel<HID, DIM><<<dim3(DIM / 32, HID / 32), 256>>>(w2, w2q, W2S);

    rmsnorm_router_kernel<<<N_TOK, 256>>>(x, nw, rw, out);
    topk_select_kernel<<<1, 1024>>>();
    compact_kernel<<<N_TOK / 256, 256>>>();

    gemm_i8<0, DIM><<<dim3(HID / BN, KSEL / BM), 256, GSMEM_BYTES>>>(b1, nullptr, nullptr, nullptr);
    gemm_i8<1, HID><<<dim3(DIM / BN, KSEL / BM), 256, GSMEM_BYTES>>>(b2, x, gamma, out);
}

// round 5
// speedup vs baseline: 2.3298x; 2.3298x over previous
#include <cuda_runtime.h>
#include <cuda_bf16.h>
#include <cuda_fp16.h>
#include <cstdint>

#define N_TOK 8192
#define DIM   2048
#define HID   8192
#define KSEL  4096

#define S1W   64.0f
#define IS1W  (1.0f / 64.0f)
#define S2W   128.0f
#define IS2W  (1.0f / 128.0f)

// ---------------- scratch (device globals; no allocation allowed) -----------
__device__ uint8_t g_w1f[(size_t)HID * DIM];   // W1^T [HID][DIM] e4m3 (x64)
__device__ uint8_t g_w2f[(size_t)DIM * HID];   // W2^T [DIM][HID] e4m3 (x128)
__device__ uint8_t g_xn [(size_t)N_TOK * DIM]; // x_norm e4m3
__device__ uint8_t g_h  [(size_t)KSEL * HID];  // gelu(h) e4m3
__device__ float    g_logits[N_TOK];
__device__ int      g_sel[KSEL];
__device__ unsigned g_thr_key;
__device__ int      g_cnt_greater;
__device__ int      g_c_gt, g_c_tie;

// ---------------- helpers ---------------------------------------------------
__device__ __forceinline__ float gelu_exact(float v) {
    return 0.5f * v * (1.0f + erff(v * 0.70710678118654752f));
}
__device__ __forceinline__ unsigned float_key(float f) {
    unsigned u = __float_as_uint(f);
    return (u & 0x80000000u) ? ~u : (u | 0x80000000u);
}
__device__ __forceinline__ uint16_t pack_e4m3x2(float lo, float hi) {
    uint16_t d;
    asm("cvt.rn.satfinite.e4m3x2.f32 %0, %1, %2;" : "=h"(d) : "f"(hi), "f"(lo));
    return d;
}
__device__ __forceinline__ uint32_t pack_e4m3x4(float a, float b, float c, float d) {
    return (uint32_t)pack_e4m3x2(a, b) | ((uint32_t)pack_e4m3x2(c, d) << 16);
}

// ---------------- transpose + fp32->e4m3 (scaled) ----------------------------
// in: [R][C] f32 ; out: [C][R] e4m3 bytes, value*scale
template<int R, int C>
__global__ __launch_bounds__(256) void transconv8_kernel(
    const float* __restrict__ in, uint8_t* __restrict__ outp, float scale)
{
    __shared__ float t[32][33];
    const int n0 = blockIdx.x * 32;
    const int k0 = blockIdx.y * 32;
    const int tx = threadIdx.x & 31;
    const int ty = threadIdx.x >> 5;
    #pragma unroll
    for (int i = 0; i < 4; i++) {
        int k = k0 + ty + 8 * i;
        t[tx][ty + 8 * i] = in[(size_t)k * C + n0 + tx];
    }
    __syncthreads();
    const int r = threadIdx.x >> 3;
    const int q = (threadIdx.x & 7) * 4;
    uint32_t v = pack_e4m3x4(t[r][q] * scale, t[r][q+1] * scale,
                             t[r][q+2] * scale, t[r][q+3] * scale);
    *reinterpret_cast<uint32_t*>(outp + (size_t)(n0 + r) * R + k0 + q) = v;
}

// ---------------- RMSNorm + router logit + x passthrough ---------------------
__device__ __forceinline__ float block_reduce_sum256(float v, float* red) {
    __syncthreads();
    int lane = threadIdx.x & 31, warp = threadIdx.x >> 5;
    #pragma unroll
    for (int o = 16; o > 0; o >>= 1) v += __shfl_xor_sync(0xffffffffu, v, o);
    if (lane == 0) red[warp] = v;
    __syncthreads();
    if (threadIdx.x == 0) {
        float s = 0.f;
        #pragma unroll
        for (int i = 0; i < 8; i++) s += red[i];
        red[8] = s;
    }
    __syncthreads();
    return red[8];
}

__global__ __launch_bounds__(256) void rmsnorm_router_kernel(
    const float* __restrict__ x, const float* __restrict__ nw,
    const float* __restrict__ rw, float* __restrict__ out)
{
    __shared__ float red[9];
    int row = blockIdx.x;
    int tid = threadIdx.x;
    const float4* x4 = reinterpret_cast<const float4*>(x + (size_t)row * DIM);
    float4 v0 = x4[tid];
    float4 v1 = x4[tid + 256];
    float ss = v0.x*v0.x + v0.y*v0.y + v0.z*v0.z + v0.w*v0.w +
               v1.x*v1.x + v1.y*v1.y + v1.z*v1.z + v1.w*v1.w;
    float tot = block_reduce_sum256(ss, red);
    float rms = rsqrtf(tot * (1.0f / DIM) + 1e-6f);

    float4* o4 = reinterpret_cast<float4*>(out + (size_t)row * DIM);
    uint32_t* xn4 = reinterpret_cast<uint32_t*>(g_xn + (size_t)row * DIM);
    float logit = 0.f;
    {
        int c = tid * 4;
        float n0 = v0.x * rms * nw[c+0];
        float n1 = v0.y * rms * nw[c+1];
        float n2 = v0.z * rms * nw[c+2];
        float n3 = v0.w * rms * nw[c+3];
        logit += n0*rw[c+0] + n1*rw[c+1] + n2*rw[c+2] + n3*rw[c+3];
        xn4[tid] = pack_e4m3x4(n0, n1, n2, n3);
        o4[tid] = v0;
    }
    {
        int c = (tid + 256) * 4;
        float n0 = v1.x * rms * nw[c+0];
        float n1 = v1.y * rms * nw[c+1];
        float n2 = v1.z * rms * nw[c+2];
        float n3 = v1.w * rms * nw[c+3];
        logit += n0*rw[c+0] + n1*rw[c+1] + n2*rw[c+2] + n3*rw[c+3];
        xn4[tid + 256] = pack_e4m3x4(n0, n1, n2, n3);
        o4[tid + 256] = v1;
    }
    float lt = block_reduce_sum256(logit, red);
    if (tid == 0) g_logits[row] = lt;
}

// ---------------- exact k-th largest via 4-pass radix select -----------------
__global__ __launch_bounds__(1024) void topk_select_kernel() {
    __shared__ unsigned skey[N_TOK];
    __shared__ int hist[256];
    __shared__ int s_krem, s_bin, s_cnt;
    int tid = threadIdx.x;
    const int NT = 1024;
    for (int i = tid; i < N_TOK; i += NT) skey[i] = float_key(g_logits[i]);
    if (tid == 0) s_krem = KSEL;
    __syncthreads();

    unsigned prefix = 0, mask = 0;
    for (int shift = 24; shift >= 0; shift -= 8) {
        if (tid < 256) hist[tid] = 0;
        __syncthreads();
        for (int i = tid; i < N_TOK; i += NT) {
            unsigned u = skey[i];
            if ((u & mask) == prefix) atomicAdd(&hist[(u >> shift) & 255], 1);
        }
        __syncthreads();
        if (tid == 0) {
            int krem = s_krem, cum = 0, b = 0;
            for (int j = 255; j >= 0; --j) {
                if (cum + hist[j] >= krem) { b = j; break; }
                cum += hist[j];
            }
            s_krem = krem - cum;
            s_bin = b;
        }
        __syncthreads();
        prefix |= ((unsigned)s_bin) << shift;
        mask   |= 0xFFu << shift;
        __syncthreads();
    }
    if (tid == 0) s_cnt = 0;
    __syncthreads();
    int c = 0;
    for (int i = tid; i < N_TOK; i += NT) if (skey[i] > prefix) c++;
    atomicAdd(&s_cnt, c);
    __syncthreads();
    if (tid == 0) {
        g_thr_key = prefix;
        g_cnt_greater = s_cnt;
        g_c_gt = 0; g_c_tie = 0;
    }
}

__global__ void compact_kernel() {
    int i = blockIdx.x * blockDim.x + threadIdx.x;
    if (i >= N_TOK) return;
    unsigned u = float_key(g_logits[i]);
    unsigned thr = g_thr_key;
    if (u > thr) {
        int p = atomicAdd(&g_c_gt, 1);
        g_sel[p] = i;
    } else if (u == thr) {
        int t = atomicAdd(&g_c_tie, 1);
        int need = KSEL - g_cnt_greater;
        if (t < need) g_sel[g_cnt_greater + t] = i;
    }
}

// ====================== FP8 mma.sync GEMM (f16 accumulate) ===================
// Tile 128(M) x 128(N) x 64(K bytes), 8 warps (4Mx2N), 4-stage cp.async.
#define BM 128
#define BN 128
#define BK 64
#define NSTG 4
#define ROWB 80                       // padded smem row stride (bytes)
#define A_STG (BM * ROWB)             // 10240
#define B_STG (BN * ROWB)             // 10240
#define GSMEM_BYTES (NSTG * (A_STG + B_STG))   // 81920

__device__ __forceinline__ void cp16(uint32_t s, const void* g) {
    asm volatile("cp.async.cg.shared.global [%0], [%1], 16;" :: "r"(s), "l"(g));
}
__device__ __forceinline__ void ldmx4(uint32_t& r0, uint32_t& r1, uint32_t& r2, uint32_t& r3, uint32_t a) {
    asm volatile("ldmatrix.sync.aligned.m8n8.x4.shared.b16 {%0,%1,%2,%3}, [%4];"
                 : "=r"(r0), "=r"(r1), "=r"(r2), "=r"(r3) : "r"(a));
}
// fp8 e4m3 inputs, f16 accumulator: c = {c01, c23} packed half2
__device__ __forceinline__ void mma_fp8h(uint32_t* c, const uint32_t* a, uint32_t b0, uint32_t b1) {
    asm volatile("mma.sync.aligned.m16n8k32.row.col.f16.e4m3.e4m3.f16 "
                 "{%0,%1},{%2,%3,%4,%5},{%6,%7},{%0,%1};"
                 : "+r"(c[0]), "+r"(c[1])
                 : "r"(a[0]), "r"(a[1]), "r"(a[2]), "r"(a[3]), "r"(b0), "r"(b1));
}

// EPI==0: A = g_xn gathered by g_sel, B = g_w1f[HID][DIM], out = g_h (gelu, e4m3)
// EPI==1: A = g_h,                    B = g_w2f[DIM][HID], out = x + gamma*(acc/S2+b2)
template<int EPI, int Kdim>
__global__ __launch_bounds__(256, 2) void gemm_fp8(
    const float* __restrict__ bias, const float* __restrict__ x,
    const float* __restrict__ gamma, float* __restrict__ out)
{
    extern __shared__ char dsm[];
    const uint32_t smA = (uint32_t)__cvta_generic_to_shared(dsm);
    const uint32_t smB = smA + NSTG * A_STG;
    const int tid = threadIdx.x;
    const int lane = tid & 31;
    const int warp = tid >> 5;
    const int bn = blockIdx.x, bm = blockIdx.y;

    const uint8_t* Asrc = (EPI == 0) ? g_xn : g_h;
    const uint8_t* Bsrc = (EPI == 0) ? g_w1f : g_w2f;

    const int r0 = tid >> 2;          // 0..63
    const int cb = (tid & 3) * 16;    // byte chunk in 64B row
    const uint8_t* ap[2]; uint32_t asw[2];
    const uint8_t* bp[2]; uint32_t bsw[2];
    #pragma unroll
    for (int j = 0; j < 2; j++) {
        int r = r0 + 64 * j;
        int gm = bm * BM + r;
        long grow = (EPI == 0) ? (long)g_sel[gm] : (long)gm;
        ap[j] = Asrc + (size_t)grow * Kdim + cb;
        asw[j] = smA + r * ROWB + cb;
        bp[j] = Bsrc + (size_t)(bn * BN + r) * Kdim + cb;
        bsw[j] = smB + r * ROWB + cb;
    }

    auto load_stage = [&](int s, int kt) {
        const size_t ko = (size_t)kt * BK;
        const uint32_t ao = s * A_STG, bo = s * B_STG;
        cp16(asw[0] + ao, ap[0] + ko);
        cp16(asw[1] + ao, ap[1] + ko);
        cp16(bsw[0] + bo, bp[0] + ko);
        cp16(bsw[1] + bo, bp[1] + ko);
        asm volatile("cp.async.commit_group;");
    };

    uint32_t acc[2][8][2];
    #pragma unroll
    for (int i = 0; i < 2; i++)
        #pragma unroll
        for (int j = 0; j < 8; j++) {
            acc[i][j][0] = 0u; acc[i][j][1] = 0u;
        }

    const int wm = (warp & 3) * 32;
    const int wn = (warp >> 2) * 64;
    const int frow = lane & 15;            // row within 16-row frag
    const int fcol = (lane >> 4) * 16;     // 16B half select

    const int KT = Kdim / BK;
    load_stage(0, 0);
    load_stage(1, 1);
    load_stage(2, 2);

    for (int kt = 0; kt < KT; ++kt) {
        const int s = kt & (NSTG - 1);
        asm volatile("cp.async.wait_group %0;" :: "n"(NSTG - 2));
        __syncthreads();
        if (kt + NSTG - 1 < KT) load_stage((kt + NSTG - 1) & (NSTG - 1), kt + NSTG - 1);

        const uint32_t aBase = smA + s * A_STG;
        const uint32_t bBase = smB + s * B_STG;
        #pragma unroll
        for (int ks = 0; ks < 2; ++ks) {
            uint32_t af[2][4];
            #pragma unroll
            for (int mi = 0; mi < 2; ++mi)
                ldmx4(af[mi][0], af[mi][1], af[mi][2], af[mi][3],
                      aBase + (wm + mi * 16 + frow) * ROWB + fcol + ks * 32);
            #pragma unroll
            for (int ni = 0; ni < 4; ++ni) {
                uint32_t b0, b1, b2, b3;
                ldmx4(b0, b1, b2, b3,
                      bBase + (wn + ni * 16 + frow) * ROWB + fcol + ks * 32);
                #pragma unroll
                for (int mi = 0; mi < 2; ++mi) {
                    mma_fp8h(acc[mi][2 * ni],     af[mi], b0, b2);
                    mma_fp8h(acc[mi][2 * ni + 1], af[mi], b1, b3);
                }
            }
        }
        __syncthreads();
    }

    // ---------------- epilogue ----------------
    const int r  = lane >> 2;
    const int cc = (lane & 3) * 2;
    if (EPI == 0) {
        #pragma unroll
        for (int mi = 0; mi < 2; ++mi) {
            const int gm0 = bm * BM + wm + mi * 16 + r;
            #pragma unroll
            for (int nj = 0; nj < 8; ++nj) {
                const int gn = bn * BN + wn + nj * 8 + cc;
                const float b0 = bias[gn], b1v = bias[gn + 1];
                float2 f01 = __half22float2(*reinterpret_cast<__half2*>(&acc[mi][nj][0]));
                float2 f23 = __half22float2(*reinterpret_cast<__half2*>(&acc[mi][nj][1]));
                float v0 = gelu_exact(f01.x * IS1W + b0);
                float v1 = gelu_exact(f01.y * IS1W + b1v);
                float v2 = gelu_exact(f23.x * IS1W + b0);
                float v3 = gelu_exact(f23.y * IS1W + b1v);
                *reinterpret_cast<uint16_t*>(&g_h[(size_t)gm0 * HID + gn])       = pack_e4m3x2(v0, v1);
                *reinterpret_cast<uint16_t*>(&g_h[(size_t)(gm0 + 8) * HID + gn]) = pack_e4m3x2(v2, v3);
            }
        }
    } else {
        #pragma unroll
        for (int mi = 0; mi < 2; ++mi) {
            const int m0 = bm * BM + wm + mi * 16 + r;
            const int tok0 = g_sel[m0];
            const int tok1 = g_sel[m0 + 8];
            #pragma unroll
            for (int nj = 0; nj < 8; ++nj) {
                const int gn = bn * BN + wn + nj * 8 + cc;
                const float bb0 = bias[gn], bb1 = bias[gn + 1];
                const float gg0 = gamma[gn], gg1 = gamma[gn + 1];
                const float* xr0 = x + (size_t)tok0 * DIM + gn;
                const float* xr1 = x + (size_t)tok1 * DIM + gn;
                float2 f01 = __half22float2(*reinterpret_cast<__half2*>(&acc[mi][nj][0]));
                float2 f23 = __half22float2(*reinterpret_cast<__half2*>(&acc[mi][nj][1]));
                float2 o0, o1;
                o0.x = xr0[0] + gg0 * (f01.x * IS2W + bb0);
                o0.y = xr0[1] + gg1 * (f01.y * IS2W + bb1);
                o1.x = xr1[0] + gg0 * (f23.x * IS2W + bb0);
                o1.y = xr1[1] + gg1 * (f23.y * IS2W + bb1);
                *reinterpret_cast<float2*>(out + (size_t)tok0 * DIM + gn) = o0;
                *reinterpret_cast<float2*>(out + (size_t)tok1 * DIM + gn) = o1;
            }
        }
    }
}

// ---------------- launch -----------------------------------------------------
extern "C" void kernel_launch(void* const* d_in, const int* in_sizes, int n_in,
                              void* d_out, int out_size) {
    const float* x     = (const float*)d_in[0];
    const float* nw    = (const float*)d_in[1];
    const float* rw    = (const float*)d_in[2];
    const float* w1    = (const float*)d_in[4];
    const float* b1    = (const float*)d_in[5];
    const float* w2    = (const float*)d_in[6];
    const float* b2    = (const float*)d_in[7];
    const float* gamma = (const float*)d_in[8];
    float* out = (float*)d_out;

    cudaFuncSetAttribute(gemm_fp8<0, DIM>, cudaFuncAttributeMaxDynamicSharedMemorySize, GSMEM_BYTES);
    cudaFuncSetAttribute(gemm_fp8<1, HID>, cudaFuncAttributeMaxDynamicSharedMemorySize, GSMEM_BYTES);

    uint8_t* w1f; cudaGetSymbolAddress((void**)&w1f, g_w1f);
    uint8_t* w2f; cudaGetSymbolAddress((void**)&w2f, g_w2f);

    // W1 [DIM][HID] f32 -> g_w1f [HID][DIM] e4m3 * S1W
    transconv8_kernel<DIM, HID><<<dim3(HID / 32, DIM / 32), 256>>>(w1, w1f, S1W);
    // W2 [HID][DIM] f32 -> g_w2f [DIM][HID] e4m3 * S2W
    transconv8_kernel<HID, DIM><<<dim3(DIM / 32, HID / 32), 256>>>(w2, w2f, S2W);

    rmsnorm_router_kernel<<<N_TOK, 256>>>(x, nw, rw, out);
    topk_select_kernel<<<1, 1024>>>();
    compact_kernel<<<N_TOK / 256, 256>>>();

    gemm_fp8<0, DIM><<<dim3(HID / BN, KSEL / BM), 256, GSMEM_BYTES>>>(b1, nullptr, nullptr, nullptr);
    gemm_fp8<1, HID><<<dim3(DIM / BN, KSEL / BM), 256, GSMEM_BYTES>>>(b2, x, gamma, out);
}

// round 6
// speedup vs baseline: 2.4213x; 1.0393x over previous
#include <cuda_runtime.h>
#include <cuda_bf16.h>
#include <cuda_fp16.h>
#include <cstdint>

#define N_TOK 8192
#define DIM   2048
#define HID   8192
#define KSEL  4096

#define S1W   64.0f
#define IS1W  (1.0f / 64.0f)
#define S2W   128.0f
#define IS2W  (1.0f / 128.0f)

#define MT1   2048      // GEMM1 tiles (32 bm x 64 bn)
#define MT2   512       // GEMM2 tiles (32 bm x 16 bn)
#define NTILES (MT1 + MT2)

// ---------------- scratch (device globals; no allocation allowed) -----------
__device__ uint8_t g_w1f[(size_t)HID * DIM];   // W1^T [HID][DIM] e4m3 (x64)
__device__ uint8_t g_w2f[(size_t)DIM * HID];   // W2^T [DIM][HID] e4m3 (x128)
__device__ uint8_t g_xn [(size_t)N_TOK * DIM]; // x_norm e4m3
__device__ uint8_t g_h  [(size_t)KSEL * HID];  // gelu(h) e4m3
__device__ float    g_logits[N_TOK];
__device__ int      g_sel[KSEL];
__device__ unsigned g_thr_key;
__device__ int      g_cnt_greater;
__device__ int      g_c_gt, g_c_tie;
__device__ int      g_tile;        // work queue head
__device__ int      g_mdone[32];   // GEMM1 n-tiles completed per m-tile

// ---------------- helpers ---------------------------------------------------
__device__ __forceinline__ float gelu_exact(float v) {
    return 0.5f * v * (1.0f + erff(v * 0.70710678118654752f));
}
__device__ __forceinline__ unsigned float_key(float f) {
    unsigned u = __float_as_uint(f);
    return (u & 0x80000000u) ? ~u : (u | 0x80000000u);
}
__device__ __forceinline__ uint16_t pack_e4m3x2(float lo, float hi) {
    uint16_t d;
    asm("cvt.rn.satfinite.e4m3x2.f32 %0, %1, %2;" : "=h"(d) : "f"(hi), "f"(lo));
    return d;
}
__device__ __forceinline__ uint32_t pack_e4m3x4(float a, float b, float c, float d) {
    return (uint32_t)pack_e4m3x2(a, b) | ((uint32_t)pack_e4m3x2(c, d) << 16);
}

// ---------------- transpose + fp32->e4m3 (scaled), coalesced -----------------
// in: [R][C] f32 ; out: [C][R] e4m3, value*scale. Tile: 128(k=R-dim) x 32(n=C-dim)
template<int R, int C>
__global__ __launch_bounds__(256) void transconv8_kernel(
    const float* __restrict__ in, uint8_t* __restrict__ outp, float scale)
{
    __shared__ float s[32][132];
    const int n0 = blockIdx.x * 32;
    const int k0 = blockIdx.y * 128;
    #pragma unroll
    for (int i = 0; i < 16; i++) {
        int idx = threadIdx.x + 256 * i;
        int row = idx >> 5;   // k 0..127
        int col = idx & 31;   // n 0..31
        s[col][row] = in[(size_t)(k0 + row) * C + n0 + col];
    }
    __syncthreads();
    const int n  = threadIdx.x >> 3;
    const int ch = (threadIdx.x & 7) * 16;
    uint32_t w[4];
    #pragma unroll
    for (int j = 0; j < 4; j++)
        w[j] = pack_e4m3x4(s[n][ch + 4*j] * scale,     s[n][ch + 4*j + 1] * scale,
                           s[n][ch + 4*j + 2] * scale, s[n][ch + 4*j + 3] * scale);
    *reinterpret_cast<uint4*>(outp + (size_t)(n0 + n) * R + k0 + ch) =
        make_uint4(w[0], w[1], w[2], w[3]);
}

// ---------------- RMSNorm + router logit + x passthrough ---------------------
__device__ __forceinline__ float block_reduce_sum256(float v, float* red) {
    __syncthreads();
    int lane = threadIdx.x & 31, warp = threadIdx.x >> 5;
    #pragma unroll
    for (int o = 16; o > 0; o >>= 1) v += __shfl_xor_sync(0xffffffffu, v, o);
    if (lane == 0) red[warp] = v;
    __syncthreads();
    if (threadIdx.x == 0) {
        float s = 0.f;
        #pragma unroll
        for (int i = 0; i < 8; i++) s += red[i];
        red[8] = s;
    }
    __syncthreads();
    return red[8];
}

__global__ __launch_bounds__(256) void rmsnorm_router_kernel(
    const float* __restrict__ x, const float* __restrict__ nw,
    const float* __restrict__ rw, float* __restrict__ out)
{
    __shared__ float red[9];
    int row = blockIdx.x;
    int tid = threadIdx.x;
    const float4* x4 = reinterpret_cast<const float4*>(x + (size_t)row * DIM);
    float4 v0 = x4[tid];
    float4 v1 = x4[tid + 256];
    float ss = v0.x*v0.x + v0.y*v0.y + v0.z*v0.z + v0.w*v0.w +
               v1.x*v1.x + v1.y*v1.y + v1.z*v1.z + v1.w*v1.w;
    float tot = block_reduce_sum256(ss, red);
    float rms = rsqrtf(tot * (1.0f / DIM) + 1e-6f);

    float4* o4 = reinterpret_cast<float4*>(out + (size_t)row * DIM);
    uint32_t* xn4 = reinterpret_cast<uint32_t*>(g_xn + (size_t)row * DIM);
    float logit = 0.f;
    {
        int c = tid * 4;
        float n0 = v0.x * rms * nw[c+0];
        float n1 = v0.y * rms * nw[c+1];
        float n2 = v0.z * rms * nw[c+2];
        float n3 = v0.w * rms * nw[c+3];
        logit += n0*rw[c+0] + n1*rw[c+1] + n2*rw[c+2] + n3*rw[c+3];
        xn4[tid] = pack_e4m3x4(n0, n1, n2, n3);
        o4[tid] = v0;
    }
    {
        int c = (tid + 256) * 4;
        float n0 = v1.x * rms * nw[c+0];
        float n1 = v1.y * rms * nw[c+1];
        float n2 = v1.z * rms * nw[c+2];
        float n3 = v1.w * rms * nw[c+3];
        logit += n0*rw[c+0] + n1*rw[c+1] + n2*rw[c+2] + n3*rw[c+3];
        xn4[tid + 256] = pack_e4m3x4(n0, n1, n2, n3);
        o4[tid + 256] = v1;
    }
    float lt = block_reduce_sum256(logit, red);
    if (tid == 0) g_logits[row] = lt;
}

// ---------------- exact k-th largest via 4-pass radix select -----------------
__global__ __launch_bounds__(1024) void topk_select_kernel() {
    __shared__ unsigned skey[N_TOK];
    __shared__ int hist[256];
    __shared__ int s_krem, s_bin, s_cnt;
    int tid = threadIdx.x;
    const int NT = 1024;
    for (int i = tid; i < N_TOK; i += NT) skey[i] = float_key(g_logits[i]);
    if (tid == 0) s_krem = KSEL;
    // reset fused-GEMM bookkeeping for this invocation
    if (tid < 32) g_mdone[tid] = 0;
    if (tid == 32) g_tile = 0;
    __syncthreads();

    unsigned prefix = 0, mask = 0;
    for (int shift = 24; shift >= 0; shift -= 8) {
        if (tid < 256) hist[tid] = 0;
        __syncthreads();
        for (int i = tid; i < N_TOK; i += NT) {
            unsigned u = skey[i];
            if ((u & mask) == prefix) atomicAdd(&hist[(u >> shift) & 255], 1);
        }
        __syncthreads();
        if (tid == 0) {
            int krem = s_krem, cum = 0, b = 0;
            for (int j = 255; j >= 0; --j) {
                if (cum + hist[j] >= krem) { b = j; break; }
                cum += hist[j];
            }
            s_krem = krem - cum;
            s_bin = b;
        }
        __syncthreads();
        prefix |= ((unsigned)s_bin) << shift;
        mask   |= 0xFFu << shift;
        __syncthreads();
    }
    if (tid == 0) s_cnt = 0;
    __syncthreads();
    int c = 0;
    for (int i = tid; i < N_TOK; i += NT) if (skey[i] > prefix) c++;
    atomicAdd(&s_cnt, c);
    __syncthreads();
    if (tid == 0) {
        g_thr_key = prefix;
        g_cnt_greater = s_cnt;
        g_c_gt = 0; g_c_tie = 0;
    }
}

__global__ void compact_kernel() {
    int i = blockIdx.x * blockDim.x + threadIdx.x;
    if (i >= N_TOK) return;
    unsigned u = float_key(g_logits[i]);
    unsigned thr = g_thr_key;
    if (u > thr) {
        int p = atomicAdd(&g_c_gt, 1);
        g_sel[p] = i;
    } else if (u == thr) {
        int t = atomicAdd(&g_c_tie, 1);
        int need = KSEL - g_cnt_greater;
        if (t < need) g_sel[g_cnt_greater + t] = i;
    }
}

// ====================== fused persistent FP8 GEMM (f16 acc) ==================
#define BM 128
#define BN 128
#define BK 64
#define NSTG 4
#define ROWB 80
#define A_STG (BM * ROWB)
#define B_STG (BN * ROWB)
#define GSMEM_BYTES (NSTG * (A_STG + B_STG))   // 81920

__device__ __forceinline__ void cp16(uint32_t s, const void* g) {
    asm volatile("cp.async.cg.shared.global [%0], [%1], 16;" :: "r"(s), "l"(g));
}
__device__ __forceinline__ void ldmx4(uint32_t& r0, uint32_t& r1, uint32_t& r2, uint32_t& r3, uint32_t a) {
    asm volatile("ldmatrix.sync.aligned.m8n8.x4.shared.b16 {%0,%1,%2,%3}, [%4];"
                 : "=r"(r0), "=r"(r1), "=r"(r2), "=r"(r3) : "r"(a));
}
__device__ __forceinline__ void mma_fp8h(uint32_t* c, const uint32_t* a, uint32_t b0, uint32_t b1) {
    asm volatile("mma.sync.aligned.m16n8k32.row.col.f16.e4m3.e4m3.f16 "
                 "{%0,%1},{%2,%3,%4,%5},{%6,%7},{%0,%1};"
                 : "+r"(c[0]), "+r"(c[1])
                 : "r"(a[0]), "r"(a[1]), "r"(a[2]), "r"(a[3]), "r"(b0), "r"(b1));
}

// EPI==0: A = g_xn gathered by g_sel, B = g_w1f, K=DIM, out = g_h (gelu, e4m3)
// EPI==1: A = g_h,                    B = g_w2f, K=HID, out = x + gamma*(acc/S2+b2)
template<int EPI, int Kdim>
__device__ __forceinline__ void gemm_tile(
    int bm, int bn, uint32_t smA, uint32_t smB, int tid,
    const float* __restrict__ bias, const float* __restrict__ x,
    const float* __restrict__ gamma, float* __restrict__ out)
{
    const int lane = tid & 31;
    const int warp = tid >> 5;

    const uint8_t* Asrc = (EPI == 0) ? g_xn : g_h;
    const uint8_t* Bsrc = (EPI == 0) ? g_w1f : g_w2f;

    const int r0 = tid >> 2;
    const int cb = (tid & 3) * 16;
    const uint8_t* ap[2]; uint32_t asw[2];
    const uint8_t* bp[2]; uint32_t bsw[2];
    #pragma unroll
    for (int j = 0; j < 2; j++) {
        int r = r0 + 64 * j;
        int gm = bm * BM + r;
        long grow = (EPI == 0) ? (long)g_sel[gm] : (long)gm;
        ap[j] = Asrc + (size_t)grow * Kdim + cb;
        asw[j] = smA + r * ROWB + cb;
        bp[j] = Bsrc + (size_t)(bn * BN + r) * Kdim + cb;
        bsw[j] = smB + r * ROWB + cb;
    }

    auto load_stage = [&](int s, int kt) {
        const size_t ko = (size_t)kt * BK;
        const uint32_t ao = s * A_STG, bo = s * B_STG;
        cp16(asw[0] + ao, ap[0] + ko);
        cp16(asw[1] + ao, ap[1] + ko);
        cp16(bsw[0] + bo, bp[0] + ko);
        cp16(bsw[1] + bo, bp[1] + ko);
        asm volatile("cp.async.commit_group;");
    };

    uint32_t acc[2][8][2];
    #pragma unroll
    for (int i = 0; i < 2; i++)
        #pragma unroll
        for (int j = 0; j < 8; j++) { acc[i][j][0] = 0u; acc[i][j][1] = 0u; }

    const int wm = (warp & 3) * 32;
    const int wn = (warp >> 2) * 64;
    const int frow = lane & 15;
    const int fcol = (lane >> 4) * 16;

    const int KT = Kdim / BK;
    load_stage(0, 0);
    load_stage(1, 1);
    load_stage(2, 2);

    for (int kt = 0; kt < KT; ++kt) {
        const int s = kt & (NSTG - 1);
        asm volatile("cp.async.wait_group %0;" :: "n"(NSTG - 2));
        __syncthreads();     // all finished iter kt-1 -> safe to prefetch its stage
        if (kt + NSTG - 1 < KT) load_stage((kt + NSTG - 1) & (NSTG - 1), kt + NSTG - 1);

        const uint32_t aBase = smA + s * A_STG;
        const uint32_t bBase = smB + s * B_STG;
        #pragma unroll
        for (int ks = 0; ks < 2; ++ks) {
            uint32_t af[2][4];
            #pragma unroll
            for (int mi = 0; mi < 2; ++mi)
                ldmx4(af[mi][0], af[mi][1], af[mi][2], af[mi][3],
                      aBase + (wm + mi * 16 + frow) * ROWB + fcol + ks * 32);
            #pragma unroll
            for (int ni = 0; ni < 4; ++ni) {
                uint32_t b0, b1, b2, b3;
                ldmx4(b0, b1, b2, b3,
                      bBase + (wn + ni * 16 + frow) * ROWB + fcol + ks * 32);
                #pragma unroll
                for (int mi = 0; mi < 2; ++mi) {
                    mma_fp8h(acc[mi][2 * ni],     af[mi], b0, b2);
                    mma_fp8h(acc[mi][2 * ni + 1], af[mi], b1, b3);
                }
            }
        }
    }
    asm volatile("cp.async.wait_group 0;");

    // ---------------- epilogue ----------------
    const int r  = lane >> 2;
    const int cc = (lane & 3) * 2;
    if (EPI == 0) {
        #pragma unroll
        for (int mi = 0; mi < 2; ++mi) {
            const int gm0 = bm * BM + wm + mi * 16 + r;
            #pragma unroll
            for (int nj = 0; nj < 8; ++nj) {
                const int gn = bn * BN + wn + nj * 8 + cc;
                const float b0 = bias[gn], b1v = bias[gn + 1];
                float2 f01 = __half22float2(*reinterpret_cast<__half2*>(&acc[mi][nj][0]));
                float2 f23 = __half22float2(*reinterpret_cast<__half2*>(&acc[mi][nj][1]));
                float v0 = gelu_exact(f01.x * IS1W + b0);
                float v1 = gelu_exact(f01.y * IS1W + b1v);
                float v2 = gelu_exact(f23.x * IS1W + b0);
                float v3 = gelu_exact(f23.y * IS1W + b1v);
                *reinterpret_cast<uint16_t*>(&g_h[(size_t)gm0 * HID + gn])       = pack_e4m3x2(v0, v1);
                *reinterpret_cast<uint16_t*>(&g_h[(size_t)(gm0 + 8) * HID + gn]) = pack_e4m3x2(v2, v3);
            }
        }
        __threadfence();
        __syncthreads();
        if (tid == 0) atomicAdd(&g_mdone[bm], 1);
    } else {
        #pragma unroll
        for (int mi = 0; mi < 2; ++mi) {
            const int m0 = bm * BM + wm + mi * 16 + r;
            const int tok0 = g_sel[m0];
            const int tok1 = g_sel[m0 + 8];
            #pragma unroll
            for (int nj = 0; nj < 8; ++nj) {
                const int gn = bn * BN + wn + nj * 8 + cc;
                const float bb0 = bias[gn], bb1 = bias[gn + 1];
                const float gg0 = gamma[gn], gg1 = gamma[gn + 1];
                const float* xr0 = x + (size_t)tok0 * DIM + gn;
                const float* xr1 = x + (size_t)tok1 * DIM + gn;
                float2 f01 = __half22float2(*reinterpret_cast<__half2*>(&acc[mi][nj][0]));
                float2 f23 = __half22float2(*reinterpret_cast<__half2*>(&acc[mi][nj][1]));
                float2 o0, o1;
                o0.x = xr0[0] + gg0 * (f01.x * IS2W + bb0);
                o0.y = xr0[1] + gg1 * (f01.y * IS2W + bb1);
                o1.x = xr1[0] + gg0 * (f23.x * IS2W + bb0);
                o1.y = xr1[1] + gg1 * (f23.y * IS2W + bb1);
                *reinterpret_cast<float2*>(out + (size_t)tok0 * DIM + gn) = o0;
                *reinterpret_cast<float2*>(out + (size_t)tok1 * DIM + gn) = o1;
            }
        }
    }
}

__global__ __launch_bounds__(256, 2) void gemm_fused(
    const float* __restrict__ b1, const float* __restrict__ b2,
    const float* __restrict__ x, const float* __restrict__ gamma,
    float* __restrict__ out)
{
    extern __shared__ char dsm[];
    __shared__ int s_t;
    const uint32_t smA = (uint32_t)__cvta_generic_to_shared(dsm);
    const uint32_t smB = smA + NSTG * A_STG;
    const int tid = threadIdx.x;

    for (;;) {
        if (tid == 0) s_t = atomicAdd(&g_tile, 1);
        __syncthreads();                    // broadcast + smem reuse barrier
        const int t = s_t;
        if (t >= NTILES) break;
        if (t < MT1) {
            gemm_tile<0, DIM>(t >> 6, t & 63, smA, smB, tid, b1, x, gamma, out);
        } else {
            const int u = t - MT1;
            const int bm = u >> 4, bn = u & 15;
            if (tid == 0) {
                while (atomicAdd(&g_mdone[bm], 0) < 64) __nanosleep(128);
            }
            __syncthreads();
            __threadfence();
            gemm_tile<1, HID>(bm, bn, smA, smB, tid, b2, x, gamma, out);
        }
    }
}

// ---------------- launch -----------------------------------------------------
extern "C" void kernel_launch(void* const* d_in, const int* in_sizes, int n_in,
                              void* d_out, int out_size) {
    const float* x     = (const float*)d_in[0];
    const float* nw    = (const float*)d_in[1];
    const float* rw    = (const float*)d_in[2];
    const float* w1    = (const float*)d_in[4];
    const float* b1    = (const float*)d_in[5];
    const float* w2    = (const float*)d_in[6];
    const float* b2    = (const float*)d_in[7];
    const float* gamma = (const float*)d_in[8];
    float* out = (float*)d_out;

    cudaFuncSetAttribute(gemm_fused, cudaFuncAttributeMaxDynamicSharedMemorySize, GSMEM_BYTES);

    int nsm = 148;
    cudaDeviceGetAttribute(&nsm, cudaDevAttrMultiProcessorCount, 0);

    uint8_t* w1f; cudaGetSymbolAddress((void**)&w1f, g_w1f);
    uint8_t* w2f; cudaGetSymbolAddress((void**)&w2f, g_w2f);

    // W1 [DIM][HID] f32 -> g_w1f [HID][DIM] e4m3 * S1W
    transconv8_kernel<DIM, HID><<<dim3(HID / 32, DIM / 128), 256>>>(w1, w1f, S1W);
    // W2 [HID][DIM] f32 -> g_w2f [DIM][HID] e4m3 * S2W
    transconv8_kernel<HID, DIM><<<dim3(DIM / 32, HID / 128), 256>>>(w2, w2f, S2W);

    rmsnorm_router_kernel<<<N_TOK, 256>>>(x, nw, rw, out);
    topk_select_kernel<<<1, 1024>>>();
    compact_kernel<<<N_TOK / 256, 256>>>();

    gemm_fused<<<2 * nsm, 256, GSMEM_BYTES>>>(b1, b2, x, gamma, out);
}